// round 16
// baseline (speedup 1.0000x reference)
#include <cuda_runtime.h>
#include <cuda_fp16.h>
#include <math.h>

#define NN   100000
#define EE   3200000
#define IND  128
#define H1D  32
#define H2D  64
#define H3D  10
#define NBLK 391          // ceil(NN/256)
#define GEMMB 3125        // NN/32 gemm blocks (warp per 4 rows, 8 warps)
#define FILLB 12500       // EE/256 fill blocks
#define PACKN 8512        // packed weight elements (6464 mlp + 2048 gemm)
#define PACKB 34          // ceil(PACKN/256)

typedef unsigned long long ull;

// ---------------- scratch (device globals; no allocations allowed) ----------
__device__ __align__(16) __half g_t16[NN * H1D];  // (x@W)*dis rows, fp16
__device__ __align__(16) __half g_h16[NN * H1D];  // dis*relu rows, fp16
__device__ int   g_cnt[NN];           // per-dst edge counts (no self loop)
__device__ float g_dis[NN];           // (deg+1)^-1/2
__device__ int   g_ptr[NN];           // CSR row starts (exclusive)
__device__ int   g_cur[NN];           // fill cursors
__device__ int   g_bsum[512];         // scan block sums
__device__ int   g_tick;              // scan1 completion ticket
__device__ int   g_esrc[EE];          // CSR: src node per slot (4B records)
__device__ int2  g_e32[EE];           // packed (s,d) int32 per original edge
// fp16 decoder-2 records, 64B stride (32 halfs): c@halfs[0:10), n@halfs[16:26)
__device__ __align__(128) __half g_d2h[NN * 32];
// pre-packed f32x2 weights:
// [0,4096):    Wp[m][i]  m=0..3 (mu_c,lv_c,mu_n,lv_n), i=k*32+lane
// [4096,6144): D1p[d][i] d=0,1
// [6144,6464): D2p[d][i] (160 each)
__device__ __align__(16) ull g_packW[6464];
__device__ __align__(16) ull g_Wg[2048];   // gemm1 packed weights
__device__ int g_is64;

// ---------------- f32x2 helpers (sm_103a packed fp32) ----------------------
__device__ __forceinline__ ull pack2(float lo, float hi) {
    ull r; asm("mov.b64 %0,{%1,%2};" : "=l"(r) : "f"(lo), "f"(hi)); return r;
}
__device__ __forceinline__ ull fma2(ull a, ull b, ull c) {
    ull d; asm("fma.rn.f32x2 %0,%1,%2,%3;" : "=l"(d) : "l"(a), "l"(b), "l"(c)); return d;
}
__device__ __forceinline__ void unpack2(ull v, float& lo, float& hi) {
    asm("mov.b64 {%0,%1},%2;" : "=f"(lo), "=f"(hi) : "l"(v));
}
__device__ __forceinline__ float ftanh(float x) {
    float e = __expf(2.0f * x);               // inf-safe
    return 1.0f - __fdividef(2.0f, e + 1.0f);
}
__device__ __forceinline__ float dot_h2(unsigned a, unsigned b) {
    __half2 ha = *reinterpret_cast<__half2*>(&a);
    __half2 hb = *reinterpret_cast<__half2*>(&b);
    float2 fa = __half22float2(ha);
    float2 fb = __half22float2(hb);
    return fa.x * fb.x + fa.y * fb.y;
}

__device__ __forceinline__ int eidx(const int* __restrict__ w, long long pos, int is64) {
    return is64 ? w[2 * pos] : w[pos];
}

// boot: zero counts + detect dtype + PACK ALL WEIGHTS once (extra blocks).
__global__ void k_boot(const int* __restrict__ w, const float* __restrict__ W,
                       const float* __restrict__ Wmc, const float* __restrict__ Wlc,
                       const float* __restrict__ Wmn, const float* __restrict__ Wln,
                       const float* __restrict__ Wd1c, const float* __restrict__ Wd1n,
                       const float* __restrict__ Wd2c, const float* __restrict__ Wd2n) {
    if (blockIdx.x < NBLK) {
        int i = blockIdx.x * 256 + threadIdx.x;
        if (i < NN) g_cnt[i] = 0;
        if (i == 0) {
            g_tick = 0;
            int all0 = 1;
            for (int q = 0; q < 16; q++)
                if (w[2 * q + 1] != 0) all0 = 0;
            g_is64 = all0;
        }
        return;
    }
    int gidx = (blockIdx.x - NBLK) * 256 + threadIdx.x;
    if (gidx >= PACKN) return;
    if (gidx < 4096) {
        int m = gidx >> 10, i2 = gidx & 1023;
        int k = i2 >> 5, lane = i2 & 31;
        const float* src = (m == 0) ? Wmc : (m == 1) ? Wlc : (m == 2) ? Wmn : Wln;
        g_packW[gidx] = pack2(src[k * 64 + lane], src[k * 64 + lane + 32]);
    } else if (gidx < 6144) {
        int local = gidx - 4096;
        int d = local >> 10, i2 = local & 1023;
        int k = i2 >> 5, lane = i2 & 31;
        const float* src = d ? Wd1n : Wd1c;
        g_packW[gidx] = pack2(src[k * 32 + lane], src[(k + 32) * 32 + lane]);
    } else if (gidx < 6464) {
        int local = gidx - 6144;
        int d = local / 160, i2 = local % 160;
        int kp = i2 / H3D, j = i2 % H3D;
        const float* src = d ? Wd2n : Wd2c;
        g_packW[gidx] = pack2(src[(2 * kp) * H3D + j], src[(2 * kp + 1) * H3D + j]);
    } else {
        int i2 = gidx - 6464;
        int k = i2 >> 4, c2 = i2 & 15;
        g_Wg[i2] = pack2(W[k * H1D + 2 * c2], W[k * H1D + 2 * c2 + 1]);
    }
}

// Count degrees AND convert edge_index to packed int32 pairs (one int64 pass).
__global__ void k_deg(const int* __restrict__ ew) {
    int e = blockIdx.x * blockDim.x + threadIdx.x;
    if (e >= EE) return;
    int is64 = g_is64;
    int s = eidx(ew, e, is64);
    int d = eidx(ew, (long long)EE + e, is64);
    g_e32[e] = make_int2(s, d);
    atomicAdd(&g_cnt[d], 1);
}

// Block scan of g_cnt into g_ptr (+ dis fused); last block (ticket) scans
// the block sums (absorbs old scan2).
__global__ void k_scan1() {
    __shared__ int s[256];
    __shared__ int sIsLast;
    int i = blockIdx.x * 256 + threadIdx.x;
    int v = (i < NN) ? g_cnt[i] : 0;
    if (i < NN) g_dis[i] = rsqrtf((float)v + 1.0f);
    s[threadIdx.x] = v;
    __syncthreads();
    for (int o = 1; o < 256; o <<= 1) {
        int t = (threadIdx.x >= o) ? s[threadIdx.x - o] : 0;
        __syncthreads();
        s[threadIdx.x] += t;
        __syncthreads();
    }
    if (i < NN) g_ptr[i] = s[threadIdx.x];
    if (threadIdx.x == 255) g_bsum[blockIdx.x] = s[255];

    if (threadIdx.x == 0) {
        __threadfence();
        int t = atomicAdd(&g_tick, 1);
        sIsLast = (t == NBLK - 1);
    }
    __syncthreads();
    if (sIsLast) {
        __shared__ int sb[NBLK];
        __threadfence();
        for (int q = threadIdx.x; q < NBLK; q += 256) sb[q] = g_bsum[q];
        __syncthreads();
        if (threadIdx.x == 0) {
            int run = 0;
            for (int q = 0; q < NBLK; q++) { int vv = sb[q]; sb[q] = run; run += vv; }
        }
        __syncthreads();
        for (int q = threadIdx.x; q < NBLK; q += 256) g_bsum[q] = sb[q];
    }
}

__global__ void k_scan3() {
    int i = blockIdx.x * 256 + threadIdx.x;
    if (i >= NN) return;
    int start = g_ptr[i] + g_bsum[i >> 8] - g_cnt[i];
    g_ptr[i] = start;
    g_cur[i] = start;
}

// Interleaved heterogeneous kernel: blockIdx%5==0 -> gemm1 (FMA-bound),
// else CSR fill (L2/atomic-bound).
__global__ void k_fillgemm(const float* __restrict__ x) {
    __shared__ ull sWp[IND * 16];       // 16KB
    __shared__ ull sA[8][4 * 64];       // 16KB
    int tid = threadIdx.x;

    int g = blockIdx.x / 5;
    int r = blockIdx.x % 5;
    if (r != 0) {
        int e = (4 * g + (r - 1)) * 256 + tid;
        if (e < EE) {
            int2 sd = g_e32[e];
            int pos = atomicAdd(&g_cur[sd.y], 1);
            g_esrc[pos] = sd.x;
        }
        return;
    }

    // gemm1: copy pre-packed weights (vectorized)
    {
        const uint4* srcv = reinterpret_cast<const uint4*>(g_Wg);
        uint4* dstv = reinterpret_cast<uint4*>(sWp);
#pragma unroll
        for (int i = tid; i < 1024; i += 256) dstv[i] = srcv[i];
    }
    __syncthreads();

    int lane = tid & 31;
    int warp = tid >> 5;
    int row0 = (g * 8 + warp) * 4;

    int c2 = lane & 15, rg = lane >> 4;

    float xv[4][4];
#pragma unroll
    for (int rr = 0; rr < 4; rr++) {
        const float* xr = x + (size_t)(row0 + rr) * IND;
#pragma unroll
        for (int u = 0; u < 4; u++) xv[rr][u] = xr[u * 32 + lane];
    }

    ull acc0 = pack2(0.f, 0.f), acc1 = pack2(0.f, 0.f);
#pragma unroll
    for (int ch = 0; ch < 2; ch++) {
#pragma unroll
        for (int rr = 0; rr < 4; rr++)
#pragma unroll
            for (int u = 0; u < 2; u++) {
                float v = xv[rr][2 * ch + u];
                sA[warp][rr * 64 + u * 32 + lane] = pack2(v, v);
            }
        __syncwarp();
#pragma unroll 16
        for (int k = 0; k < 64; k++) {
            ull w2 = sWp[(ch * 64 + k) * 16 + c2];
            ull a0 = sA[warp][(2 * rg) * 64 + k];
            ull a1 = sA[warp][(2 * rg + 1) * 64 + k];
            acc0 = fma2(a0, w2, acc0);
            acc1 = fma2(a1, w2, acc1);
        }
        __syncwarp();
    }

    float lo0, hi0, lo1, hi1;
    unpack2(acc0, lo0, hi0);
    unpack2(acc1, lo1, hi1);
    int r0 = row0 + 2 * rg, r1 = r0 + 1;
    float d0 = g_dis[r0], d1 = g_dis[r1];
    *reinterpret_cast<__half2*>(g_t16 + (size_t)r0 * H1D + 2 * c2) =
        __floats2half2_rn(lo0 * d0, hi0 * d0);
    *reinterpret_cast<__half2*>(g_t16 + (size_t)r1 * H1D + 2 * c2) =
        __floats2half2_rn(lo1 * d1, hi1 * d1);
}

// Layer-1 aggregation: t' -> h' = fp16(dis*relu(dis*(sum+self) + b)).
__global__ void k_agg1(const float* __restrict__ b) {
    __shared__ int sE[8][32];
    int lane = threadIdx.x & 31;
    int w = threadIdx.x >> 5;
    int node = (blockIdx.x * blockDim.x + threadIdx.x) >> 5;
    if (node >= NN) return;

    int hid = lane >> 4;
    int c = lane & 15;
    int j = g_ptr[node];
    int rem = g_cnt[node];
    float dd = g_dis[node];

    float2 acc = make_float2(0.f, 0.f);
    if (hid == 0) {
        __half2 v = *reinterpret_cast<const __half2*>(g_t16 + (size_t)node * H1D + 2 * c);
        acc = __half22float2(v);
    }

    while (rem >= 32) {
        sE[w][lane] = g_esrc[j + lane];
        __syncwarp();
#pragma unroll
        for (int q = 0; q < 32; q += 2) {
            int idx = sE[w][q + hid];
            __half2 v = *reinterpret_cast<const __half2*>(g_t16 + (size_t)idx * H1D + 2 * c);
            float2 f = __half22float2(v);
            acc.x += f.x;
            acc.y += f.y;
        }
        __syncwarp();
        j += 32;
        rem -= 32;
    }
    if (rem > 0) {
        if (lane < rem) sE[w][lane] = g_esrc[j + lane];
        __syncwarp();
        int q = 0;
        for (; q + 2 <= rem; q += 2) {
            int idx = sE[w][q + hid];
            __half2 v = *reinterpret_cast<const __half2*>(g_t16 + (size_t)idx * H1D + 2 * c);
            float2 f = __half22float2(v);
            acc.x += f.x;
            acc.y += f.y;
        }
        if (q < rem && hid == 0) {
            int idx = sE[w][q];
            __half2 v = *reinterpret_cast<const __half2*>(g_t16 + (size_t)idx * H1D + 2 * c);
            float2 f = __half22float2(v);
            acc.x += f.x;
            acc.y += f.y;
        }
    }

    acc.x += __shfl_xor_sync(0xffffffffu, acc.x, 16);
    acc.y += __shfl_xor_sync(0xffffffffu, acc.y, 16);

    if (lane < 16) {
        float2 bb = *reinterpret_cast<const float2*>(b + 2 * c);
        float v0 = dd * acc.x + bb.x;
        float v1 = dd * acc.y + bb.y;
        v0 = fmaxf(v0, 0.f) * dd;
        v1 = fmaxf(v1, 0.f) * dd;
        *reinterpret_cast<__half2*>(g_h16 + (size_t)node * H1D + 2 * c) =
            __floats2half2_rn(v0, v1);
    }
}

// Fused tail: CSR-gather -> (mu,lv)x2 -> z -> decoders. Weights copied
// pre-packed from g_packW (vectorized), not re-packed per block.
__global__ void k_mlp(
    const float* __restrict__ eps_c, const float* __restrict__ eps_n,
    const float* __restrict__ bmc, const float* __restrict__ bmn,
    const float* __restrict__ blc, const float* __restrict__ bln,
    const float* __restrict__ bd1c, const float* __restrict__ bd2c,
    const float* __restrict__ bd1n, const float* __restrict__ bd2n,
    float* __restrict__ omc, float* __restrict__ omn,
    float* __restrict__ olc, float* __restrict__ oln) {
    __shared__ ull sALL[6464];          // Wp | D1p | D2p (51.7KB)
    __shared__ ull sA[8][4 * 32];
    __shared__ ull sZ4[8][4 * 32];
    __shared__ float sDv4[8][4 * 32];
    __shared__ int sE[8][32];

    int tid = threadIdx.x;
    {
        const uint4* srcv = reinterpret_cast<const uint4*>(g_packW);
        uint4* dstv = reinterpret_cast<uint4*>(sALL);
        for (int i = tid; i < 3232; i += 256) dstv[i] = srcv[i];
    }
    __syncthreads();

    int lane = tid & 31;
    int warp = tid >> 5;
    int row0 = (blockIdx.x * 8 + warp) * 4;
    if (row0 >= NN) return;

    // ---- fused layer-2 aggregation: gather h' for the 4 rows into sA ----
    int hid = lane >> 4;
    int c = lane & 15;
#pragma unroll 1
    for (int rr = 0; rr < 4; rr++) {
        int node = row0 + rr;
        int j = g_ptr[node];
        int rem = g_cnt[node];
        float dd = g_dis[node];

        float2 acc = make_float2(0.f, 0.f);
        if (hid == 0) {
            __half2 v = *reinterpret_cast<const __half2*>(g_h16 + (size_t)node * H1D + 2 * c);
            acc = __half22float2(v);
        }
        while (rem >= 32) {
            sE[warp][lane] = g_esrc[j + lane];
            __syncwarp();
#pragma unroll
            for (int q = 0; q < 32; q += 2) {
                int idx = sE[warp][q + hid];
                __half2 v = *reinterpret_cast<const __half2*>(g_h16 + (size_t)idx * H1D + 2 * c);
                float2 f = __half22float2(v);
                acc.x += f.x;
                acc.y += f.y;
            }
            __syncwarp();
            j += 32;
            rem -= 32;
        }
        if (rem > 0) {
            if (lane < rem) sE[warp][lane] = g_esrc[j + lane];
            __syncwarp();
            int q = 0;
            for (; q + 2 <= rem; q += 2) {
                int idx = sE[warp][q + hid];
                __half2 v = *reinterpret_cast<const __half2*>(g_h16 + (size_t)idx * H1D + 2 * c);
                float2 f = __half22float2(v);
                acc.x += f.x;
                acc.y += f.y;
            }
            if (q < rem && hid == 0) {
                int idx = sE[warp][q];
                __half2 v = *reinterpret_cast<const __half2*>(g_h16 + (size_t)idx * H1D + 2 * c);
                float2 f = __half22float2(v);
                acc.x += f.x;
                acc.y += f.y;
            }
            __syncwarp();
        }
        acc.x += __shfl_xor_sync(0xffffffffu, acc.x, 16);
        acc.y += __shfl_xor_sync(0xffffffffu, acc.y, 16);
        if (lane < 16) {
            float a0 = dd * acc.x, a1 = dd * acc.y;
            sA[warp][rr * 32 + 2 * c]     = pack2(a0, a0);
            sA[warp][rr * 32 + 2 * c + 1] = pack2(a1, a1);
        }
    }
    __syncwarp();

    int jj = lane < H3D ? lane : 0;

#pragma unroll
    for (int half = 0; half < 2; half++) {
        const ull* Wm = sALL + (half * 2) * 1024;
        const ull* Wl = sALL + (half * 2 + 1) * 1024;
        const ull* D1 = sALL + 4096 + half * 1024;
        const ull* D2 = sALL + 6144 + half * 160;
        const float* bm = half ? bmn : bmc;
        const float* bl = half ? bln : blc;
        const float* b1 = half ? bd1n : bd1c;
        const float* b2 = half ? bd2n : bd2c;
        const float* eps = half ? eps_n : eps_c;
        float* om = half ? omn : omc;
        float* ol = half ? oln : olc;

        ull m01[4], l01[4];
        {
            ull bmp = pack2(bm[lane], bm[lane + 32]);
            ull blp = pack2(bl[lane], bl[lane + 32]);
#pragma unroll
            for (int rr = 0; rr < 4; rr++) { m01[rr] = bmp; l01[rr] = blp; }
        }
#pragma unroll 8
        for (int k = 0; k < 32; k++) {
            ull wm = Wm[k * 32 + lane];
            ull wl = Wl[k * 32 + lane];
#pragma unroll
            for (int rr = 0; rr < 4; rr++) {
                ull a2 = sA[warp][rr * 32 + k];
                m01[rr] = fma2(a2, wm, m01[rr]);
                l01[rr] = fma2(a2, wl, l01[rr]);
            }
        }

#pragma unroll
        for (int rr = 0; rr < 4; rr++) {
            size_t i = row0 + rr;
            float m0, m1, l0, l1;
            unpack2(m01[rr], m0, m1);
            unpack2(l01[rr], l0, l1);
            om[i * H2D + lane] = m0;
            om[i * H2D + lane + 32] = m1;
            ol[i * H2D + lane] = l0;
            ol[i * H2D + lane + 32] = l1;
            float z0 = m0 + eps[i * H2D + lane] * __expf(0.5f * l0);
            float z1 = m1 + eps[i * H2D + lane + 32] * __expf(0.5f * l1);
            sZ4[warp][rr * 32 + lane] = pack2(z0, z1);
        }
        __syncwarp();

        float b1v = b1[lane];
        ull acc1[4];
#pragma unroll
        for (int rr = 0; rr < 4; rr++) acc1[rr] = pack2(b1v, 0.f);
#pragma unroll 8
        for (int k = 0; k < 32; k++) {
            ull d1w = D1[k * 32 + lane];
#pragma unroll
            for (int rr = 0; rr < 4; rr++)
                acc1[rr] = fma2(sZ4[warp][rr * 32 + k], d1w, acc1[rr]);
        }
#pragma unroll
        for (int rr = 0; rr < 4; rr++) {
            float s0, s1;
            unpack2(acc1[rr], s0, s1);
            sDv4[warp][rr * 32 + lane] = ftanh(s0 + s1);
        }
        __syncwarp();

        float b2v = b2[jj];
        ull acc2[4];
#pragma unroll
        for (int rr = 0; rr < 4; rr++) acc2[rr] = pack2(b2v, 0.f);
#pragma unroll 8
        for (int kp = 0; kp < 16; kp++) {
            ull d2w = D2[kp * H3D + jj];
#pragma unroll
            for (int rr = 0; rr < 4; rr++) {
                ull dp = *reinterpret_cast<const ull*>(&sDv4[warp][rr * 32 + 2 * kp]);
                acc2[rr] = fma2(dp, d2w, acc2[rr]);
            }
        }
#pragma unroll
        for (int rr = 0; rr < 4; rr++) {
            float s0, s1;
            unpack2(acc2[rr], s0, s1);
            float v = ftanh(s0 + s1);
            if (lane < H3D)
                g_d2h[(size_t)(row0 + rr) * 32 + half * 16 + lane] = __float2half_rn(v);
        }
        __syncwarp();
    }
}

// Lane-pair decode on 64B-aligned fp16 records: even lane c-dot, odd lane n-dot.
__global__ void k_decode(float* __restrict__ oc, float* __restrict__ on) {
    long long t = (long long)blockIdx.x * blockDim.x + threadIdx.x;
    int e = (int)(t >> 1);
    int part = (int)t & 1;
    if (e >= EE) return;
    int2 sd = g_e32[e];

    const char* pa = reinterpret_cast<const char*>(g_d2h + (size_t)sd.x * 32) + part * 32;
    const char* pb = reinterpret_cast<const char*>(g_d2h + (size_t)sd.y * 32) + part * 32;
    uint4 a0 = *reinterpret_cast<const uint4*>(pa);
    unsigned a1 = *reinterpret_cast<const unsigned*>(pa + 16);
    uint4 b0 = *reinterpret_cast<const uint4*>(pb);
    unsigned b1 = *reinterpret_cast<const unsigned*>(pb + 16);

    float acc = dot_h2(a0.x, b0.x) + dot_h2(a0.y, b0.y) + dot_h2(a0.z, b0.z)
              + dot_h2(a0.w, b0.w) + dot_h2(a1, b1);
    float r = __fdividef(1.f, 1.f + __expf(-acc));
    float* outp = part ? on : oc;
    outp[e] = r;
}

extern "C" void kernel_launch(void* const* d_in, const int* in_sizes, int n_in,
                              void* d_out, int out_size) {
    const float* x        = (const float*)d_in[0];
    const int*   ew       = (const int*)d_in[1];
    const float* eps_c    = (const float*)d_in[2];
    const float* eps_n    = (const float*)d_in[3];
    const float* W_shared = (const float*)d_in[4];
    const float* b_shared = (const float*)d_in[5];
    const float* Wmc = (const float*)d_in[6],  *bmc = (const float*)d_in[7];
    const float* Wmn = (const float*)d_in[8],  *bmn = (const float*)d_in[9];
    const float* Wlc = (const float*)d_in[10], *blc = (const float*)d_in[11];
    const float* Wln = (const float*)d_in[12], *bln = (const float*)d_in[13];
    const float* Wd1c = (const float*)d_in[14], *bd1c = (const float*)d_in[15];
    const float* Wd2c = (const float*)d_in[16], *bd2c = (const float*)d_in[17];
    const float* Wd1n = (const float*)d_in[18], *bd1n = (const float*)d_in[19];
    const float* Wd2n = (const float*)d_in[20], *bd2n = (const float*)d_in[21];

    float* out  = (float*)d_out;
    float* oewc = out;
    float* oewn = out + (size_t)EE;
    float* omc  = out + 2 * (size_t)EE;
    float* omn  = omc + (size_t)NN * H2D;
    float* olc  = omn + (size_t)NN * H2D;
    float* oln  = olc + (size_t)NN * H2D;

    k_boot<<<NBLK + PACKB, 256>>>(ew, W_shared, Wmc, Wlc, Wmn, Wln,
                                  Wd1c, Wd1n, Wd2c, Wd2n);
    k_deg<<<(EE + 255) / 256, 256>>>(ew);
    k_scan1<<<NBLK, 256>>>();
    k_scan3<<<NBLK, 256>>>();
    k_fillgemm<<<GEMMB + FILLB, 256>>>(x);             // interleaved gemm+fill
    k_agg1<<<(NN + 7) / 8, 256>>>(b_shared);           // t' -> h'
    k_mlp<<<NN / 32, 256>>>(eps_c, eps_n, bmc, bmn, blc, bln,
                            bd1c, bd2c, bd1n, bd2n,
                            omc, omn, olc, oln);
    k_decode<<<(2 * EE + 255) / 256, 256>>>(oewc, oewn);
}

// round 17
// speedup vs baseline: 1.0293x; 1.0293x over previous
#include <cuda_runtime.h>
#include <cuda_fp16.h>
#include <math.h>

#define NN   100000
#define EE   3200000
#define IND  128
#define H1D  32
#define H2D  64
#define H3D  10
#define NBLK 391          // ceil(NN/256)
#define GEMMB 3125        // NN/32 gemm blocks (warp per 4 rows, 8 warps)
#define FILLB 12500       // EE/256 fill blocks

typedef unsigned long long ull;

// ---------------- scratch (device globals; no allocations allowed) ----------
__device__ __align__(16) __half g_t16[NN * H1D];  // (x@W)*dis rows, fp16
__device__ __align__(16) __half g_h16[NN * H1D];  // dis*relu rows, fp16
__device__ int   g_cnt[NN];           // per-dst edge counts (no self loop)
__device__ float g_dis[NN];           // (deg+1)^-1/2
__device__ int   g_ptr[NN];           // CSR row starts (exclusive)
__device__ int   g_cur[NN];           // fill cursors
__device__ int   g_bsum[512];         // scan block sums
__device__ int   g_tick;              // scan1 completion ticket
__device__ int   g_esrc[EE];          // CSR: src node per slot (4B records)
__device__ int2  g_e32[EE];           // packed (s,d) int32 per original edge
// fp16 decoder-2 records, 64B stride (32 halfs): c@halfs[0:10), n@halfs[16:26)
__device__ __align__(128) __half g_d2h[NN * 32];
__device__ int g_is64;

// ---------------- f32x2 helpers (sm_103a packed fp32) ----------------------
__device__ __forceinline__ ull pack2(float lo, float hi) {
    ull r; asm("mov.b64 %0,{%1,%2};" : "=l"(r) : "f"(lo), "f"(hi)); return r;
}
__device__ __forceinline__ ull fma2(ull a, ull b, ull c) {
    ull d; asm("fma.rn.f32x2 %0,%1,%2,%3;" : "=l"(d) : "l"(a), "l"(b), "l"(c)); return d;
}
__device__ __forceinline__ void unpack2(ull v, float& lo, float& hi) {
    asm("mov.b64 {%0,%1},%2;" : "=f"(lo), "=f"(hi) : "l"(v));
}
__device__ __forceinline__ float ftanh(float x) {
    float e = __expf(2.0f * x);               // inf-safe
    return 1.0f - __fdividef(2.0f, e + 1.0f);
}
__device__ __forceinline__ float dot_h2(unsigned a, unsigned b) {
    __half2 ha = *reinterpret_cast<__half2*>(&a);
    __half2 hb = *reinterpret_cast<__half2*>(&b);
    float2 fa = __half22float2(ha);
    float2 fb = __half22float2(hb);
    return fa.x * fb.x + fa.y * fb.y;
}
// accumulate 4 halfs (uint2) into float4
__device__ __forceinline__ void acc_h4(float4& acc, uint2 v) {
    float2 f0 = __half22float2(*reinterpret_cast<__half2*>(&v.x));
    float2 f1 = __half22float2(*reinterpret_cast<__half2*>(&v.y));
    acc.x += f0.x; acc.y += f0.y; acc.z += f1.x; acc.w += f1.y;
}

__device__ __forceinline__ int eidx(const int* __restrict__ w, long long pos, int is64) {
    return is64 ? w[2 * pos] : w[pos];
}

// Detect int64 vs int32 edge_index + zero counts + ticket (fused).
__global__ void k_boot(const int* __restrict__ w) {
    int i = blockIdx.x * 256 + threadIdx.x;
    if (i < NN) g_cnt[i] = 0;
    if (i == 0) {
        g_tick = 0;
        int all0 = 1;
        for (int q = 0; q < 16; q++)
            if (w[2 * q + 1] != 0) all0 = 0;
        g_is64 = all0;
    }
}

// Count degrees AND convert edge_index to packed int32 pairs (one int64 pass).
__global__ void k_deg(const int* __restrict__ ew) {
    int e = blockIdx.x * blockDim.x + threadIdx.x;
    if (e >= EE) return;
    int is64 = g_is64;
    int s = eidx(ew, e, is64);
    int d = eidx(ew, (long long)EE + e, is64);
    g_e32[e] = make_int2(s, d);
    atomicAdd(&g_cnt[d], 1);
}

// Block scan of g_cnt into g_ptr (+ dis fused); last block (ticket) scans
// the block sums (absorbs old scan2).
__global__ void k_scan1() {
    __shared__ int s[256];
    __shared__ int sIsLast;
    int i = blockIdx.x * 256 + threadIdx.x;
    int v = (i < NN) ? g_cnt[i] : 0;
    if (i < NN) g_dis[i] = rsqrtf((float)v + 1.0f);
    s[threadIdx.x] = v;
    __syncthreads();
    for (int o = 1; o < 256; o <<= 1) {
        int t = (threadIdx.x >= o) ? s[threadIdx.x - o] : 0;
        __syncthreads();
        s[threadIdx.x] += t;
        __syncthreads();
    }
    if (i < NN) g_ptr[i] = s[threadIdx.x];
    if (threadIdx.x == 255) g_bsum[blockIdx.x] = s[255];

    if (threadIdx.x == 0) {
        __threadfence();
        int t = atomicAdd(&g_tick, 1);
        sIsLast = (t == NBLK - 1);
    }
    __syncthreads();
    if (sIsLast) {
        __shared__ int sb[NBLK];
        __threadfence();
        for (int q = threadIdx.x; q < NBLK; q += 256) sb[q] = g_bsum[q];
        __syncthreads();
        if (threadIdx.x == 0) {
            int run = 0;
            for (int q = 0; q < NBLK; q++) { int vv = sb[q]; sb[q] = run; run += vv; }
        }
        __syncthreads();
        for (int q = threadIdx.x; q < NBLK; q += 256) g_bsum[q] = sb[q];
    }
}

__global__ void k_scan3() {
    int i = blockIdx.x * 256 + threadIdx.x;
    if (i >= NN) return;
    int start = g_ptr[i] + g_bsum[i >> 8] - g_cnt[i];
    g_ptr[i] = start;
    g_cur[i] = start;
}

// Interleaved heterogeneous kernel: blockIdx%5==0 -> gemm1 (FMA-bound),
// else CSR fill (L2/atomic-bound). Every wave mixes both roles.
__global__ void k_fillgemm(const float* __restrict__ x, const float* __restrict__ W) {
    __shared__ ull sWp[IND * 16];       // 16KB
    __shared__ ull sA[8][4 * 64];       // 16KB
    int tid = threadIdx.x;

    int g = blockIdx.x / 5;
    int r = blockIdx.x % 5;
    if (r != 0) {
        int e = (4 * g + (r - 1)) * 256 + tid;
        if (e < EE) {
            int2 sd = g_e32[e];
            int pos = atomicAdd(&g_cur[sd.y], 1);
            g_esrc[pos] = sd.x;
        }
        return;
    }

    for (int i = tid; i < IND * 16; i += 256) {
        int k = i >> 4, c2i = i & 15;
        sWp[i] = pack2(W[k * H1D + 2 * c2i], W[k * H1D + 2 * c2i + 1]);
    }
    __syncthreads();

    int lane = tid & 31;
    int warp = tid >> 5;
    int row0 = (g * 8 + warp) * 4;

    int c2 = lane & 15, rg = lane >> 4;

    float xv[4][4];
#pragma unroll
    for (int rr = 0; rr < 4; rr++) {
        const float* xr = x + (size_t)(row0 + rr) * IND;
#pragma unroll
        for (int u = 0; u < 4; u++) xv[rr][u] = xr[u * 32 + lane];
    }

    ull acc0 = pack2(0.f, 0.f), acc1 = pack2(0.f, 0.f);
#pragma unroll
    for (int ch = 0; ch < 2; ch++) {
#pragma unroll
        for (int rr = 0; rr < 4; rr++)
#pragma unroll
            for (int u = 0; u < 2; u++) {
                float v = xv[rr][2 * ch + u];
                sA[warp][rr * 64 + u * 32 + lane] = pack2(v, v);
            }
        __syncwarp();
#pragma unroll 16
        for (int k = 0; k < 64; k++) {
            ull w2 = sWp[(ch * 64 + k) * 16 + c2];
            ull a0 = sA[warp][(2 * rg) * 64 + k];
            ull a1 = sA[warp][(2 * rg + 1) * 64 + k];
            acc0 = fma2(a0, w2, acc0);
            acc1 = fma2(a1, w2, acc1);
        }
        __syncwarp();
    }

    float lo0, hi0, lo1, hi1;
    unpack2(acc0, lo0, hi0);
    unpack2(acc1, lo1, hi1);
    int r0 = row0 + 2 * rg, r1 = r0 + 1;
    float d0 = g_dis[r0], d1 = g_dis[r1];
    *reinterpret_cast<__half2*>(g_t16 + (size_t)r0 * H1D + 2 * c2) =
        __floats2half2_rn(lo0 * d0, hi0 * d0);
    *reinterpret_cast<__half2*>(g_t16 + (size_t)r1 * H1D + 2 * c2) =
        __floats2half2_rn(lo1 * d1, hi1 * d1);
}

// Layer-1 aggregation: t' -> h' = fp16(dis*relu(dis*(sum+self) + b)).
// Warp per dst node, 4 edges/iter: 8 lanes per edge, lane loads 8B (4 halfs).
__global__ void k_agg1(const float* __restrict__ b) {
    __shared__ int sE[8][32];
    int lane = threadIdx.x & 31;
    int w = threadIdx.x >> 5;
    int node = (blockIdx.x * blockDim.x + threadIdx.x) >> 5;
    if (node >= NN) return;

    int eid = lane >> 3;    // edge slot within group of 4
    int c4 = lane & 7;      // uint2 column (4 halfs)
    int j = g_ptr[node];
    int rem = g_cnt[node];
    float dd = g_dis[node];

    float4 acc = make_float4(0.f, 0.f, 0.f, 0.f);
    if (eid == 0)
        acc_h4(acc, *reinterpret_cast<const uint2*>(g_t16 + (size_t)node * H1D + 4 * c4));

    while (rem >= 32) {
        sE[w][lane] = g_esrc[j + lane];
        __syncwarp();
#pragma unroll
        for (int q = 0; q < 32; q += 4) {
            int idx = sE[w][q + eid];
            acc_h4(acc, *reinterpret_cast<const uint2*>(g_t16 + (size_t)idx * H1D + 4 * c4));
        }
        __syncwarp();
        j += 32;
        rem -= 32;
    }
    if (rem > 0) {
        if (lane < rem) sE[w][lane] = g_esrc[j + lane];
        __syncwarp();
        for (int q = 0; q < rem; q += 4) {
            if (eid < rem - q) {
                int idx = sE[w][q + eid];
                acc_h4(acc, *reinterpret_cast<const uint2*>(g_t16 + (size_t)idx * H1D + 4 * c4));
            }
        }
    }

#pragma unroll
    for (int o = 8; o < 32; o <<= 1) {
        acc.x += __shfl_xor_sync(0xffffffffu, acc.x, o);
        acc.y += __shfl_xor_sync(0xffffffffu, acc.y, o);
        acc.z += __shfl_xor_sync(0xffffffffu, acc.z, o);
        acc.w += __shfl_xor_sync(0xffffffffu, acc.w, o);
    }

    if (lane < 8) {
        float4 bb = *reinterpret_cast<const float4*>(b + 4 * c4);
        float v0 = fmaxf(dd * acc.x + bb.x, 0.f) * dd;
        float v1 = fmaxf(dd * acc.y + bb.y, 0.f) * dd;
        float v2 = fmaxf(dd * acc.z + bb.z, 0.f) * dd;
        float v3 = fmaxf(dd * acc.w + bb.w, 0.f) * dd;
        __half2 h0 = __floats2half2_rn(v0, v1);
        __half2 h1 = __floats2half2_rn(v2, v3);
        uint2 outv;
        outv.x = *reinterpret_cast<unsigned*>(&h0);
        outv.y = *reinterpret_cast<unsigned*>(&h1);
        *reinterpret_cast<uint2*>(g_h16 + (size_t)node * H1D + 4 * c4) = outv;
    }
}

// Fused tail: CSR-gather (layer-2 agg of h', 4 edges/iter) -> (mu,lv)x2 -> z
// -> decoders (row-batched).
__global__ void k_mlp(
    const float* __restrict__ eps_c, const float* __restrict__ eps_n,
    const float* __restrict__ Wmc, const float* __restrict__ bmc,
    const float* __restrict__ Wmn, const float* __restrict__ bmn,
    const float* __restrict__ Wlc, const float* __restrict__ blc,
    const float* __restrict__ Wln, const float* __restrict__ bln,
    const float* __restrict__ Wd1c, const float* __restrict__ bd1c,
    const float* __restrict__ Wd2c, const float* __restrict__ bd2c,
    const float* __restrict__ Wd1n, const float* __restrict__ bd1n,
    const float* __restrict__ Wd2n, const float* __restrict__ bd2n,
    float* __restrict__ omc, float* __restrict__ omn,
    float* __restrict__ olc, float* __restrict__ oln) {
    __shared__ ull sWp[4][H1D * 32];
    __shared__ ull sD1p[2][32 * 32];
    __shared__ ull sD2p[2][16 * H3D];
    __shared__ ull sA[8][4 * 32];
    __shared__ ull sZ4[8][4 * 32];
    __shared__ float sDv4[8][4 * 32];
    __shared__ int sE[8][32];

    int tid = threadIdx.x;
    for (int i = tid; i < 1024; i += 256) {
        int k = i >> 5, lane = i & 31;
        sWp[0][i] = pack2(Wmc[k * 64 + lane], Wmc[k * 64 + lane + 32]);
        sWp[1][i] = pack2(Wlc[k * 64 + lane], Wlc[k * 64 + lane + 32]);
        sWp[2][i] = pack2(Wmn[k * 64 + lane], Wmn[k * 64 + lane + 32]);
        sWp[3][i] = pack2(Wln[k * 64 + lane], Wln[k * 64 + lane + 32]);
        sD1p[0][i] = pack2(Wd1c[k * 32 + lane], Wd1c[(k + 32) * 32 + lane]);
        sD1p[1][i] = pack2(Wd1n[k * 32 + lane], Wd1n[(k + 32) * 32 + lane]);
    }
    for (int i = tid; i < 16 * H3D; i += 256) {
        int kp = i / H3D, j = i % H3D;
        sD2p[0][i] = pack2(Wd2c[(2 * kp) * H3D + j], Wd2c[(2 * kp + 1) * H3D + j]);
        sD2p[1][i] = pack2(Wd2n[(2 * kp) * H3D + j], Wd2n[(2 * kp + 1) * H3D + j]);
    }
    __syncthreads();

    int lane = tid & 31;
    int warp = tid >> 5;
    int row0 = (blockIdx.x * 8 + warp) * 4;
    if (row0 >= NN) return;

    // ---- fused layer-2 aggregation: gather h' for the 4 rows into sA ----
    int eid = lane >> 3;
    int c4 = lane & 7;
#pragma unroll 1
    for (int rr = 0; rr < 4; rr++) {
        int node = row0 + rr;
        int j = g_ptr[node];
        int rem = g_cnt[node];
        float dd = g_dis[node];

        float4 acc = make_float4(0.f, 0.f, 0.f, 0.f);
        if (eid == 0)
            acc_h4(acc, *reinterpret_cast<const uint2*>(g_h16 + (size_t)node * H1D + 4 * c4));

        while (rem >= 32) {
            sE[warp][lane] = g_esrc[j + lane];
            __syncwarp();
#pragma unroll
            for (int q = 0; q < 32; q += 4) {
                int idx = sE[warp][q + eid];
                acc_h4(acc, *reinterpret_cast<const uint2*>(g_h16 + (size_t)idx * H1D + 4 * c4));
            }
            __syncwarp();
            j += 32;
            rem -= 32;
        }
        if (rem > 0) {
            if (lane < rem) sE[warp][lane] = g_esrc[j + lane];
            __syncwarp();
            for (int q = 0; q < rem; q += 4) {
                if (eid < rem - q) {
                    int idx = sE[warp][q + eid];
                    acc_h4(acc, *reinterpret_cast<const uint2*>(g_h16 + (size_t)idx * H1D + 4 * c4));
                }
            }
            __syncwarp();
        }

#pragma unroll
        for (int o = 8; o < 32; o <<= 1) {
            acc.x += __shfl_xor_sync(0xffffffffu, acc.x, o);
            acc.y += __shfl_xor_sync(0xffffffffu, acc.y, o);
            acc.z += __shfl_xor_sync(0xffffffffu, acc.z, o);
            acc.w += __shfl_xor_sync(0xffffffffu, acc.w, o);
        }
        if (lane < 8) {
            float a0 = dd * acc.x, a1 = dd * acc.y, a2 = dd * acc.z, a3 = dd * acc.w;
            sA[warp][rr * 32 + 4 * c4 + 0] = pack2(a0, a0);
            sA[warp][rr * 32 + 4 * c4 + 1] = pack2(a1, a1);
            sA[warp][rr * 32 + 4 * c4 + 2] = pack2(a2, a2);
            sA[warp][rr * 32 + 4 * c4 + 3] = pack2(a3, a3);
        }
    }
    __syncwarp();

    int jj = lane < H3D ? lane : 0;

#pragma unroll
    for (int half = 0; half < 2; half++) {
        const ull* Wm = sWp[half * 2];
        const ull* Wl = sWp[half * 2 + 1];
        const ull* D1 = sD1p[half];
        const ull* D2 = sD2p[half];
        const float* bm = half ? bmn : bmc;
        const float* bl = half ? bln : blc;
        const float* b1 = half ? bd1n : bd1c;
        const float* b2 = half ? bd2n : bd2c;
        const float* eps = half ? eps_n : eps_c;
        float* om = half ? omn : omc;
        float* ol = half ? oln : olc;

        ull m01[4], l01[4];
        {
            ull bmp = pack2(bm[lane], bm[lane + 32]);
            ull blp = pack2(bl[lane], bl[lane + 32]);
#pragma unroll
            for (int rr = 0; rr < 4; rr++) { m01[rr] = bmp; l01[rr] = blp; }
        }
#pragma unroll 8
        for (int k = 0; k < 32; k++) {
            ull wm = Wm[k * 32 + lane];
            ull wl = Wl[k * 32 + lane];
#pragma unroll
            for (int rr = 0; rr < 4; rr++) {
                ull a2 = sA[warp][rr * 32 + k];
                m01[rr] = fma2(a2, wm, m01[rr]);
                l01[rr] = fma2(a2, wl, l01[rr]);
            }
        }

#pragma unroll
        for (int rr = 0; rr < 4; rr++) {
            size_t i = row0 + rr;
            float m0, m1, l0, l1;
            unpack2(m01[rr], m0, m1);
            unpack2(l01[rr], l0, l1);
            om[i * H2D + lane] = m0;
            om[i * H2D + lane + 32] = m1;
            ol[i * H2D + lane] = l0;
            ol[i * H2D + lane + 32] = l1;
            float z0 = m0 + eps[i * H2D + lane] * __expf(0.5f * l0);
            float z1 = m1 + eps[i * H2D + lane + 32] * __expf(0.5f * l1);
            sZ4[warp][rr * 32 + lane] = pack2(z0, z1);
        }
        __syncwarp();

        float b1v = b1[lane];
        ull acc1[4];
#pragma unroll
        for (int rr = 0; rr < 4; rr++) acc1[rr] = pack2(b1v, 0.f);
#pragma unroll 8
        for (int k = 0; k < 32; k++) {
            ull d1w = D1[k * 32 + lane];
#pragma unroll
            for (int rr = 0; rr < 4; rr++)
                acc1[rr] = fma2(sZ4[warp][rr * 32 + k], d1w, acc1[rr]);
        }
#pragma unroll
        for (int rr = 0; rr < 4; rr++) {
            float s0, s1;
            unpack2(acc1[rr], s0, s1);
            sDv4[warp][rr * 32 + lane] = ftanh(s0 + s1);
        }
        __syncwarp();

        float b2v = b2[jj];
        ull acc2[4];
#pragma unroll
        for (int rr = 0; rr < 4; rr++) acc2[rr] = pack2(b2v, 0.f);
#pragma unroll 8
        for (int kp = 0; kp < 16; kp++) {
            ull d2w = D2[kp * H3D + jj];
#pragma unroll
            for (int rr = 0; rr < 4; rr++) {
                ull dp = *reinterpret_cast<const ull*>(&sDv4[warp][rr * 32 + 2 * kp]);
                acc2[rr] = fma2(dp, d2w, acc2[rr]);
            }
        }
#pragma unroll
        for (int rr = 0; rr < 4; rr++) {
            float s0, s1;
            unpack2(acc2[rr], s0, s1);
            float v = ftanh(s0 + s1);
            if (lane < H3D)
                g_d2h[(size_t)(row0 + rr) * 32 + half * 16 + lane] = __float2half_rn(v);
        }
        __syncwarp();
    }
}

// Lane-pair decode on 64B-aligned fp16 records: even lane c-dot, odd lane n-dot.
__global__ void k_decode(float* __restrict__ oc, float* __restrict__ on) {
    long long t = (long long)blockIdx.x * blockDim.x + threadIdx.x;
    int e = (int)(t >> 1);
    int part = (int)t & 1;
    if (e >= EE) return;
    int2 sd = g_e32[e];

    const char* pa = reinterpret_cast<const char*>(g_d2h + (size_t)sd.x * 32) + part * 32;
    const char* pb = reinterpret_cast<const char*>(g_d2h + (size_t)sd.y * 32) + part * 32;
    uint4 a0 = *reinterpret_cast<const uint4*>(pa);
    unsigned a1 = *reinterpret_cast<const unsigned*>(pa + 16);
    uint4 b0 = *reinterpret_cast<const uint4*>(pb);
    unsigned b1 = *reinterpret_cast<const unsigned*>(pb + 16);

    float acc = dot_h2(a0.x, b0.x) + dot_h2(a0.y, b0.y) + dot_h2(a0.z, b0.z)
              + dot_h2(a0.w, b0.w) + dot_h2(a1, b1);
    float r = __fdividef(1.f, 1.f + __expf(-acc));
    float* outp = part ? on : oc;
    outp[e] = r;
}

extern "C" void kernel_launch(void* const* d_in, const int* in_sizes, int n_in,
                              void* d_out, int out_size) {
    const float* x        = (const float*)d_in[0];
    const int*   ew       = (const int*)d_in[1];
    const float* eps_c    = (const float*)d_in[2];
    const float* eps_n    = (const float*)d_in[3];
    const float* W_shared = (const float*)d_in[4];
    const float* b_shared = (const float*)d_in[5];
    const float* Wmc = (const float*)d_in[6],  *bmc = (const float*)d_in[7];
    const float* Wmn = (const float*)d_in[8],  *bmn = (const float*)d_in[9];
    const float* Wlc = (const float*)d_in[10], *blc = (const float*)d_in[11];
    const float* Wln = (const float*)d_in[12], *bln = (const float*)d_in[13];
    const float* Wd1c = (const float*)d_in[14], *bd1c = (const float*)d_in[15];
    const float* Wd2c = (const float*)d_in[16], *bd2c = (const float*)d_in[17];
    const float* Wd1n = (const float*)d_in[18], *bd1n = (const float*)d_in[19];
    const float* Wd2n = (const float*)d_in[20], *bd2n = (const float*)d_in[21];

    float* out  = (float*)d_out;
    float* oewc = out;
    float* oewn = out + (size_t)EE;
    float* omc  = out + 2 * (size_t)EE;
    float* omn  = omc + (size_t)NN * H2D;
    float* olc  = omn + (size_t)NN * H2D;
    float* oln  = olc + (size_t)NN * H2D;

    k_boot<<<NBLK, 256>>>(ew);
    k_deg<<<(EE + 255) / 256, 256>>>(ew);
    k_scan1<<<NBLK, 256>>>();
    k_scan3<<<NBLK, 256>>>();
    k_fillgemm<<<GEMMB + FILLB, 256>>>(x, W_shared);   // interleaved gemm+fill
    k_agg1<<<(NN + 7) / 8, 256>>>(b_shared);           // t' -> h'
    k_mlp<<<NN / 32, 256>>>(eps_c, eps_n, Wmc, bmc, Wmn, bmn, Wlc, blc, Wln, bln,
                            Wd1c, bd1c, Wd2c, bd2c, Wd1n, bd1n, Wd2n, bd2n,
                            omc, omn, olc, oln);
    k_decode<<<(2 * EE + 255) / 256, 256>>>(oewc, oewn);
}